// round 1
// baseline (speedup 1.0000x reference)
#include <cuda_runtime.h>
#include <cuda_bf16.h>

// Top1Router: inputs [8192, 64] fp32.
// capacity = max(even(floor(1.25*8192/64)), 4) = 160
// Outputs (concatenated, fp32): combine_weights [T,E,C] then sec_mask [T,E,C].
// combine_weights has <=1 nonzero per token -> zero everything, scatter 8192 values.

#define T_TOKENS 8192
#define N_EXP    64
#define CAPACITY 160
#define C1 ((long long)T_TOKENS * N_EXP * CAPACITY)   // 83,886,080

__device__ int   g_top1[T_TOKENS];
__device__ float g_prob[T_TOKENS];

// ---------------------------------------------------------------------------
// Kernel 1: one warp per token. Coalesced loads, shuffle argmax (first-index
// tie-break, matching jnp.argmax) + sum of exp for softmax prob of the top-1.
// ---------------------------------------------------------------------------
__global__ void top1_softmax_kernel(const float* __restrict__ x) {
    int warp = (blockIdx.x * blockDim.x + threadIdx.x) >> 5;
    int lane = threadIdx.x & 31;
    if (warp >= T_TOKENS) return;

    const float* row = x + (size_t)warp * N_EXP;
    float v0 = row[lane];
    float v1 = row[lane + 32];

    // local max + argmax (lower index wins ties)
    float m;
    int mi;
    if (v0 >= v1) { m = v0; mi = lane; }
    else          { m = v1; mi = lane + 32; }

    #pragma unroll
    for (int o = 16; o > 0; o >>= 1) {
        float om  = __shfl_down_sync(0xffffffffu, m, o);
        int   omi = __shfl_down_sync(0xffffffffu, mi, o);
        if (om > m || (om == m && omi < mi)) { m = om; mi = omi; }
    }
    m  = __shfl_sync(0xffffffffu, m, 0);
    mi = __shfl_sync(0xffffffffu, mi, 0);

    // softmax prob at argmax: exp(max-max)/sum = 1/sum(exp(x-max))
    float s = __expf(v0 - m) + __expf(v1 - m);
    #pragma unroll
    for (int o = 16; o > 0; o >>= 1)
        s += __shfl_down_sync(0xffffffffu, s, o);

    if (lane == 0) {
        g_top1[warp] = mi;
        g_prob[warp] = 1.0f / s;
    }
}

// ---------------------------------------------------------------------------
// Kernel 2: single-CTA rank computation (token-ordered cumsum per expert)
// + sparse scatter. 1024 threads, 8 chunks of 1024 tokens.
// rank(t) = base[e] (tokens in earlier chunks)
//         + exclusive prefix of per-warp counts within chunk
//         + #earlier lanes in my warp with the same expert (__match_any_sync)
// ---------------------------------------------------------------------------
__global__ void rank_scatter_kernel(float* __restrict__ out, long long out_size) {
    __shared__ int base[N_EXP];
    __shared__ int hist[32][N_EXP];

    int tid  = threadIdx.x;
    int wid  = tid >> 5;
    int lane = tid & 31;

    if (tid < N_EXP) base[tid] = 0;

    #pragma unroll 1
    for (int chunk = 0; chunk < T_TOKENS / 1024; chunk++) {
        __syncthreads();                       // guard base init / prior reads
        ((int*)hist)[tid]        = 0;          // zero 2048-entry hist
        ((int*)hist)[tid + 1024] = 0;
        __syncthreads();

        int t = chunk * 1024 + tid;
        int e = g_top1[t];

        unsigned mm    = __match_any_sync(0xffffffffu, e);
        int      before = __popc(mm & ((1u << lane) - 1u));
        int      leader = __ffs(mm) - 1;
        if (lane == leader) hist[wid][e] = __popc(mm);
        __syncthreads();

        if (tid < N_EXP) {                     // serial scan over 32 warps / expert
            int s = base[tid];
            #pragma unroll
            for (int w = 0; w < 32; w++) {
                int c = hist[w][tid];
                hist[w][tid] = s;              // exclusive prefix incl. base
                s += c;
            }
            base[tid] = s;
        }
        __syncthreads();

        int rank = hist[wid][e] + before;
        if (rank < CAPACITY) {
            long long idx = (long long)t * (N_EXP * CAPACITY)
                          + (long long)e * CAPACITY + rank;
            out[idx] = g_prob[t];              // combine weight
            long long idx2 = C1 + idx;         // sec_mask (if present in buffer)
            if (idx2 < out_size) out[idx2] = 1.0f;
        }
    }
}

extern "C" void kernel_launch(void* const* d_in, const int* in_sizes, int n_in,
                              void* d_out, int out_size) {
    const float* x = (const float*)d_in[0];
    float* out = (float*)d_out;

    // 1) routing math (independent of output buffer)
    top1_softmax_kernel<<<(T_TOKENS * 32 + 255) / 256, 256>>>(x);

    // 2) zero the (poisoned) output — the HBM-bound bulk of this problem
    cudaMemsetAsync(d_out, 0, (size_t)out_size * sizeof(float), 0);

    // 3) sequential-rank + sparse scatter
    rank_scatter_kernel<<<1, 1024>>>(out, (long long)out_size);
}

// round 3
// speedup vs baseline: 1.1093x; 1.1093x over previous
#include <cuda_runtime.h>
#include <cuda_bf16.h>

// Top1Router: inputs [8192, 64] fp32.
// capacity = max(even(floor(1.25*8192/64)), 4) = 160
// Output (fp32, concatenated): combine_weights [T,E,C] then sec_mask [T,E,C].
// Exactly one nonzero per (kept) token per half -> stream zeros + scalar fixup.

#define T_TOKENS  8192
#define N_EXP     64
#define CAPACITY  160
#define ROW_FLOATS (N_EXP * CAPACITY)     // 10240
#define ROW_F4     (ROW_FLOATS / 4)       // 2560
#define N_CHUNKS   8                      // 8 x 1024 tokens
#define FILL_THREADS 512
#define ROWS_PER_CTA 8

__device__ int   g_top1[T_TOKENS];
__device__ float g_prob[T_TOKENS];
__device__ int   g_rankpart[T_TOKENS];        // within-chunk rank
__device__ int   g_cnt[N_CHUNKS][N_EXP];      // per-chunk per-expert counts

// ---------------------------------------------------------------------------
// Kernel 1: route. 8 CTAs x 1024 threads, thread-per-token.
// Pass 1: argmax (first-index tie-break). Pass 2: sum exp(x-max) -> prob=1/s.
// Then within-chunk stable rank: __match_any + per-warp hist + 64-thread scan.
// ---------------------------------------------------------------------------
__global__ void __launch_bounds__(1024) route_kernel(const float* __restrict__ x) {
    __shared__ int hist[32][N_EXP];

    int tid  = threadIdx.x;
    int wid  = tid >> 5;
    int lane = tid & 31;
    int t    = blockIdx.x * 1024 + tid;

    const float4* row = (const float4*)(x + (size_t)t * N_EXP);

    // pass 1: max + argmax (strict > keeps lowest index on ties)
    float m = -__FLT_MAX__;
    int   e = 0;
    #pragma unroll
    for (int i = 0; i < 16; i++) {
        float4 v = row[i];
        if (v.x > m) { m = v.x; e = 4 * i + 0; }
        if (v.y > m) { m = v.y; e = 4 * i + 1; }
        if (v.z > m) { m = v.z; e = 4 * i + 2; }
        if (v.w > m) { m = v.w; e = 4 * i + 3; }
    }
    // pass 2: sum of exp (rows hot in L1/L2)
    float s = 0.0f;
    #pragma unroll
    for (int i = 0; i < 16; i++) {
        float4 v = row[i];
        s += __expf(v.x - m) + __expf(v.y - m) + __expf(v.z - m) + __expf(v.w - m);
    }

    g_top1[t] = e;
    g_prob[t] = 1.0f / s;

    // within-chunk stable rank
    ((int*)hist)[tid]        = 0;
    ((int*)hist)[tid + 1024] = 0;
    __syncthreads();

    unsigned mm     = __match_any_sync(0xffffffffu, e);
    int      before = __popc(mm & ((1u << lane) - 1u));
    int      leader = __ffs(mm) - 1;
    if (lane == leader) hist[wid][e] = __popc(mm);
    __syncthreads();

    if (tid < N_EXP) {                    // exclusive scan over 32 warps
        int acc = 0;
        #pragma unroll
        for (int w = 0; w < 32; w++) {
            int c = hist[w][tid];
            hist[w][tid] = acc;
            acc += c;
        }
        g_cnt[blockIdx.x][tid] = acc;     // chunk total per expert
    }
    __syncthreads();

    g_rankpart[t] = hist[wid][e] + before;
}

// ---------------------------------------------------------------------------
// Kernel 2: fused zero-fill + sparse write. One pass over the whole output.
// Rows 0..8191 = combine (value prob), 8192..16383 = sec_mask (value 1.0).
// Each CTA redundantly builds the tiny cross-chunk base table, then streams
// float4 zeros; the thread owning the special slot rewrites it afterwards
// (same-thread program order => ordering is safe).
// ---------------------------------------------------------------------------
__global__ void __launch_bounds__(FILL_THREADS) fill_kernel(float* __restrict__ out,
                                                            int n_rows) {
    __shared__ int base[N_CHUNKS][N_EXP];

    int tid = threadIdx.x;
    if (tid < N_EXP) {                    // 64 threads: 8-step scan per expert
        int acc = 0;
        #pragma unroll
        for (int c = 0; c < N_CHUNKS; c++) {
            base[c][tid] = acc;
            acc += g_cnt[c][tid];
        }
    }
    __syncthreads();

    int row0 = blockIdx.x * ROWS_PER_CTA;

    #pragma unroll
    for (int rr = 0; rr < ROWS_PER_CTA; rr++) {
        int r = row0 + rr;
        if (r >= n_rows) break;
        int t = r & (T_TOKENS - 1);

        int e  = g_top1[t];
        int rk = g_rankpart[t] + base[t >> 10][e];
        int sp = (rk < CAPACITY) ? (e * CAPACITY + rk) : -1;   // float offset in row
        float val = (r < T_TOKENS) ? g_prob[t] : 1.0f;

        float4* o = (float4*)(out + (size_t)r * ROW_FLOATS);
        const float4 z = make_float4(0.f, 0.f, 0.f, 0.f);
        #pragma unroll
        for (int it = 0; it < ROW_F4 / FILL_THREADS; it++) {
            __stcs(&o[tid + it * FILL_THREADS], z);
        }
        // scalar fixup by the thread that zeroed that float4
        if (sp >= 0 && tid == ((sp >> 2) & (FILL_THREADS - 1))) {
            ((float*)o)[sp] = val;
        }
    }
}

extern "C" void kernel_launch(void* const* d_in, const int* in_sizes, int n_in,
                              void* d_out, int out_size) {
    const float* x = (const float*)d_in[0];
    float* out = (float*)d_out;

    int n_rows = out_size / ROW_FLOATS;   // 16384 if both halves present

    route_kernel<<<N_CHUNKS, 1024>>>(x);
    fill_kernel<<<(n_rows + ROWS_PER_CTA - 1) / ROWS_PER_CTA, FILL_THREADS>>>(out, n_rows);
}